// round 13
// baseline (speedup 1.0000x reference)
#include <cuda_runtime.h>
#include <cuda_bf16.h>
#include <cstdint>

#define HIDDEN 3584
#define RDIM   224
#define MAX_TOKENS 16384

// ---------------- scratch ----------------
__device__ __nv_bfloat16 g_wdp[RDIM * HIDDEN];     // gamma * w_down  [224][3584]
__device__ __nv_bfloat16 g_wup[HIDDEN * RDIM];     // w_up            [3584][224]
__device__ float         g_c1[RDIM];
__device__ float         g_c2[RDIM];
__device__ __nv_bfloat16 g_mid[(size_t)MAX_TOKENS * RDIM];

// ---------------- helpers ----------------
__device__ __forceinline__ uint32_t smem_u32(const void* p) {
    uint32_t a;
    asm("{ .reg .u64 t; cvta.to.shared.u64 t, %1; cvt.u32.u64 %0, t; }" : "=r"(a) : "l"(p));
    return a;
}

__device__ __forceinline__ void mma_bf16(float c[4], const uint32_t* a,
                                         uint32_t b0, uint32_t b1) {
    asm volatile(
        "mma.sync.aligned.m16n8k16.row.col.f32.bf16.bf16.f32 "
        "{%0,%1,%2,%3}, {%4,%5,%6,%7}, {%8,%9}, {%0,%1,%2,%3};\n"
        : "+f"(c[0]), "+f"(c[1]), "+f"(c[2]), "+f"(c[3])
        : "r"(a[0]), "r"(a[1]), "r"(a[2]), "r"(a[3]), "r"(b0), "r"(b1));
}

__device__ __forceinline__ void ldsm_x4(uint32_t* r, uint32_t addr) {
    asm volatile("ldmatrix.sync.aligned.m8n8.x4.shared.b16 {%0,%1,%2,%3}, [%4];"
                 : "=r"(r[0]), "=r"(r[1]), "=r"(r[2]), "=r"(r[3]) : "r"(addr));
}
__device__ __forceinline__ void ldsm_x2(uint32_t* r, uint32_t addr) {
    asm volatile("ldmatrix.sync.aligned.m8n8.x2.shared.b16 {%0,%1}, [%2];"
                 : "=r"(r[0]), "=r"(r[1]) : "r"(addr));
}

__device__ __forceinline__ float gelu_exact(float y) {
    return 0.5f * y * (1.0f + erff(y * 0.70710678118654752f));
}

__device__ __forceinline__ void cp16(void* dst_smem, const void* src_gmem) {
    uint32_t d = (uint32_t)__cvta_generic_to_shared(dst_smem);
    asm volatile("cp.async.cg.shared.global [%0], [%1], 16;\n" :: "r"(d), "l"(src_gmem));
}
#define CP_COMMIT() asm volatile("cp.async.commit_group;\n" ::: "memory")
#define CP_WAIT0()  asm volatile("cp.async.wait_group 0;\n" ::: "memory")
#define BAR_SYNC(id) asm volatile("bar.sync %0, 256;" :: "r"(id) : "memory")

// ---------------- merged prep kernel (vectorized) ----------------
__global__ void prep_all(const float* __restrict__ wd, const float* __restrict__ gamma,
                         const float* __restrict__ beta, const float* __restrict__ wu) {
    const int b = blockIdx.x, tid = threadIdx.x;
    if (b < RDIM) {
        const float4* row = (const float4*)(wd + (size_t)b * HIDDEN);
        const float4* g4  = (const float4*)gamma;
        const float4* b4  = (const float4*)beta;
        float c1 = 0.f, c2 = 0.f;
        for (int i = tid; i < HIDDEN / 4; i += 256) {
            float4 w = row[i], g = g4[i], be = b4[i];
            float p0 = g.x * w.x, p1 = g.y * w.y, p2 = g.z * w.z, p3 = g.w * w.w;
            c1 += p0 + p1 + p2 + p3;
            c2 += be.x * w.x + be.y * w.y + be.z * w.z + be.w * w.w;
            __nv_bfloat162 h0 = __floats2bfloat162_rn(p0, p1);
            __nv_bfloat162 h1 = __floats2bfloat162_rn(p2, p3);
            uint2 pk = make_uint2(*(uint32_t*)&h0, *(uint32_t*)&h1);
            *(uint2*)&g_wdp[(size_t)b * HIDDEN + i * 4] = pk;
        }
        __shared__ float s1[256], s2[256];
        s1[tid] = c1; s2[tid] = c2;
        __syncthreads();
        for (int o = 128; o > 0; o >>= 1) {
            if (tid < o) { s1[tid] += s1[tid + o]; s2[tid] += s2[tid + o]; }
            __syncthreads();
        }
        if (tid == 0) { g_c1[b] = s1[0]; g_c2[b] = s2[0]; }
    } else {
        const int blk = b - RDIM;                       // 0..31
        const int n4 = (HIDDEN * RDIM) / 4 / 32;
        const float4* src = (const float4*)wu + (size_t)blk * n4;
        for (int i = tid; i < n4; i += 256) {
            float4 v = src[i];
            __nv_bfloat162 h0 = __floats2bfloat162_rn(v.x, v.y);
            __nv_bfloat162 h1 = __floats2bfloat162_rn(v.z, v.w);
            uint2 pk = make_uint2(*(uint32_t*)&h0, *(uint32_t*)&h1);
            *(uint2*)&g_wup[((size_t)blk * n4 + i) * 4] = pk;
        }
    }
}

// ---------------- kernel 1: fused LN + down-proj + GELU ----------------
// 256 CTAs x 256 threads (8 warps), 2 CTAs/SM -> single wave on 148 SMs.
// Each CTA owns 64 tokens with its own A/B double-buffers (the proven
// round-12 "half", now an independent CTA). Warp grid 2m x 4n, tile 32x56.
#define K1_AS 72
#define K1_A64 (64 * K1_AS)
#define K1_B224 (RDIM * K1_AS)
#define K1_NCH  (HIDDEN / 64)        // 56

__global__ __launch_bounds__(256, 2)
void kernel_ln_down(const float* __restrict__ x) {
    extern __shared__ __nv_bfloat16 dsm[];
    __nv_bfloat16* sA = dsm;                     // 2 x [64][K1_AS]
    __nv_bfloat16* sB = dsm + 2 * K1_A64;        // 2 x [224][K1_AS]

    __shared__ float sS1[64][4];
    __shared__ float sS2[64][4];
    __shared__ float sMu[64], sRstd[64];
    __shared__ float sC1[RDIM], sC2[RDIM];

    const int tid  = threadIdx.x;
    const int warp = tid >> 5, lane = tid & 31;
    const int gid  = lane >> 2, tig = lane & 3;
    const int wm   = warp >> 2, wn = warp & 3;   // 2(m) x 4(n); warp tile 32x56
    const int m0   = blockIdx.x * 64;

    for (int i = tid; i < RDIM; i += 256) { sC1[i] = g_c1[i]; sC2[i] = g_c2[i]; }

    const uint32_t aU = smem_u32(sA), bU = smem_u32(sB);
    const uint32_t aLane =
        ((uint32_t)((wm * 32 + (lane & 7) + ((lane >> 3) & 1) * 8) * K1_AS
                    + (lane >> 4) * 8)) * 2u;
    uint32_t bPair[4];
    {
        const int kc = ((lane >> 3) & 1) * 8;
#pragma unroll
        for (int p = 0; p < 3; p++) {
            int nr = wn * 56 + p * 16 + (lane & 7) + ((lane >> 4) & 1) * 8;
            bPair[p] = (uint32_t)(nr * K1_AS + kc) * 2u;
        }
        int nr3 = wn * 56 + 48 + (lane & 7);
        bPair[3] = (uint32_t)(nr3 * K1_AS + kc) * 2u;
    }

    float acc[2][7][4];
#pragma unroll
    for (int a = 0; a < 2; a++)
#pragma unroll
        for (int b = 0; b < 7; b++)
#pragma unroll
            for (int c = 0; c < 4; c++) acc[a][b][c] = 0.f;

    const int rowx = tid >> 2, lq = tid & 3;     // A loader: 4 threads/row, 64 rows
    const float* xr = x + (size_t)(m0 + rowx) * HIDDEN + lq * 16;
    const int brow = tid >> 3, bc8 = tid & 7;    // B loader: 32 rows/pass x 7
    float s1 = 0.f, s2 = 0.f;

#define K1_FILL_B(buf, ko) do {                                                 \
    __nv_bfloat16* dst_ = sB + (buf) * K1_B224;                                 \
    _Pragma("unroll")                                                           \
    for (int j = 0; j < 7; j++) {                                               \
        int row_ = brow + j * 32;                                               \
        cp16(&dst_[row_ * K1_AS + bc8 * 8],                                     \
             g_wdp + (size_t)row_ * HIDDEN + (ko) + bc8 * 8);                   \
    } } while (0)

#define K1_LOAD_X(ko, v) do {                                                   \
    _Pragma("unroll")                                                           \
    for (int i = 0; i < 4; i++) (v)[i] = *(const float4*)(xr + (ko) + i * 4);   \
    } while (0)

#define K1_STORE_A(buf, v) do {                                                 \
    _Pragma("unroll")                                                           \
    for (int i = 0; i < 4; i++) {                                               \
        s1 += (v)[i].x + (v)[i].y + (v)[i].z + (v)[i].w;                        \
        s2 += (v)[i].x*(v)[i].x + (v)[i].y*(v)[i].y                             \
            + (v)[i].z*(v)[i].z + (v)[i].w*(v)[i].w;                            \
    }                                                                           \
    {                                                                           \
        __nv_bfloat16* ab_ = sA + (buf) * K1_A64;                               \
        uint4 pk;                                                               \
        __nv_bfloat162 t0 = __floats2bfloat162_rn((v)[0].x, (v)[0].y);          \
        __nv_bfloat162 t1 = __floats2bfloat162_rn((v)[0].z, (v)[0].w);          \
        __nv_bfloat162 t2 = __floats2bfloat162_rn((v)[1].x, (v)[1].y);          \
        __nv_bfloat162 t3 = __floats2bfloat162_rn((v)[1].z, (v)[1].w);          \
        pk.x = *(uint32_t*)&t0; pk.y = *(uint32_t*)&t1;                         \
        pk.z = *(uint32_t*)&t2; pk.w = *(uint32_t*)&t3;                         \
        *(uint4*)&ab_[rowx * K1_AS + lq * 16] = pk;                             \
        __nv_bfloat162 u0 = __floats2bfloat162_rn((v)[2].x, (v)[2].y);          \
        __nv_bfloat162 u1 = __floats2bfloat162_rn((v)[2].z, (v)[2].w);          \
        __nv_bfloat162 u2 = __floats2bfloat162_rn((v)[3].x, (v)[3].y);          \
        __nv_bfloat162 u3 = __floats2bfloat162_rn((v)[3].z, (v)[3].w);          \
        pk.x = *(uint32_t*)&u0; pk.y = *(uint32_t*)&u1;                         \
        pk.z = *(uint32_t*)&u2; pk.w = *(uint32_t*)&u3;                         \
        *(uint4*)&ab_[rowx * K1_AS + lq * 16 + 8] = pk;                         \
    } } while (0)

    // ---- prologue ----
    K1_FILL_B(0, 0);
    CP_COMMIT();
    {
        float4 v[4];
        K1_LOAD_X(0, v);
        K1_STORE_A(0, v);
    }
    CP_WAIT0();
    __syncthreads();

    // ---- main pipelined loop ----
    for (int it = 0; it < K1_NCH; it++) {
        const int cur = it & 1, nxt = cur ^ 1;
        const uint32_t aCur = aU + (uint32_t)(cur * K1_A64) * 2u;
        const uint32_t bCur = bU + (uint32_t)(cur * K1_B224) * 2u;

        float4 v[4];
        if (it < K1_NCH - 1) {
            const int ko = (it + 1) * 64;
            K1_FILL_B(nxt, ko);
            CP_COMMIT();
            K1_LOAD_X(ko, v);
        }

#pragma unroll
        for (int ks = 0; ks < 4; ks++) {
            const uint32_t kOff = (uint32_t)ks * 32u;
            uint32_t a0[4], a1[4];
            ldsm_x4(a0, aCur + aLane + kOff);
            ldsm_x4(a1, aCur + aLane + (uint32_t)(16 * K1_AS * 2) + kOff);
            uint32_t bf[14];
            ldsm_x4(&bf[0],  bCur + bPair[0] + kOff);
            ldsm_x4(&bf[4],  bCur + bPair[1] + kOff);
            ldsm_x4(&bf[8],  bCur + bPair[2] + kOff);
            ldsm_x2(&bf[12], bCur + bPair[3] + kOff);
#pragma unroll
            for (int nt = 0; nt < 7; nt++) {
                mma_bf16(acc[0][nt], a0, bf[2 * nt], bf[2 * nt + 1]);
                mma_bf16(acc[1][nt], a1, bf[2 * nt], bf[2 * nt + 1]);
            }
        }

        if (it < K1_NCH - 1) {
            K1_STORE_A(nxt, v);
            CP_WAIT0();
            __syncthreads();
        }
    }

    // ---- row stats ----
    sS1[rowx][lq] = s1; sS2[rowx][lq] = s2;
    __syncthreads();
    if (tid < 64) {
        float t1 = sS1[tid][0] + sS1[tid][1] + sS1[tid][2] + sS1[tid][3];
        float t2 = sS2[tid][0] + sS2[tid][1] + sS2[tid][2] + sS2[tid][3];
        float mu = t1 * (1.0f / HIDDEN);
        float var = t2 * (1.0f / HIDDEN) - mu * mu;
        sMu[tid] = mu;
        sRstd[tid] = rsqrtf(var + 1e-5f);
    }
    __syncthreads();

    // ---- epilogue: LN correction + GELU -> g_mid ----
#pragma unroll
    for (int mt = 0; mt < 2; mt++) {
        const int r0 = wm * 32 + mt * 16 + gid;
        const float mu0 = sMu[r0],     rs0 = sRstd[r0];
        const float mu1 = sMu[r0 + 8], rs1 = sRstd[r0 + 8];
#pragma unroll
        for (int nt = 0; nt < 7; nt++) {
            const int c = wn * 56 + nt * 8 + tig * 2;
            const float c1a = sC1[c], c1b = sC1[c + 1];
            const float c2a = sC2[c], c2b = sC2[c + 1];
            float y00 = rs0 * (acc[mt][nt][0] - mu0 * c1a) + c2a;
            float y01 = rs0 * (acc[mt][nt][1] - mu0 * c1b) + c2b;
            float y10 = rs1 * (acc[mt][nt][2] - mu1 * c1a) + c2a;
            float y11 = rs1 * (acc[mt][nt][3] - mu1 * c1b) + c2b;
            *(__nv_bfloat162*)&g_mid[(size_t)(m0 + r0) * RDIM + c] =
                __floats2bfloat162_rn(gelu_exact(y00), gelu_exact(y01));
            *(__nv_bfloat162*)&g_mid[(size_t)(m0 + r0 + 8) * RDIM + c] =
                __floats2bfloat162_rn(gelu_exact(y10), gelu_exact(y11));
        }
    }
#undef K1_FILL_B
#undef K1_LOAD_X
#undef K1_STORE_A
}

// ---------------- kernel 2: persistent up-proj + residual, split-half -------
// (round-12 winner, unchanged)
#define K2_AS 232
#define K2_SPLIT 5
#define K2_T64 (64 * K2_AS)

__global__ __launch_bounds__(512, 1)
void kernel_up_res(const float* __restrict__ x, const float* __restrict__ alpha_p,
                   float* __restrict__ out, int m_tiles64) {
    extern __shared__ __nv_bfloat16 smem[];
    __nv_bfloat16* sB = smem;                    // [128][K2_AS] resident w_up slice
    __nv_bfloat16* sA = smem + 128 * K2_AS;      // [2 half][2 buf][64][K2_AS]

    const int tid  = threadIdx.x;
    const int warp = tid >> 5, lane = tid & 31;
    const int gid  = lane >> 2, tig = lane & 3;
    const int half = warp >> 3;
    const int w8   = warp & 7;
    const int wm   = w8 >> 2, wn = w8 & 3;       // 2(m) x 4(n); warp tile 32x32
    const int htid = tid & 255;
    const int n0   = blockIdx.y * 128;
    const int t_begin = (blockIdx.x * m_tiles64) / K2_SPLIT;
    const int t_end   = ((blockIdx.x + 1) * m_tiles64) / K2_SPLIT;

    const float alpha = __ldg(alpha_p);
    const uint32_t bU = smem_u32(sB), aU = smem_u32(sA);
    const uint32_t aLane =
        ((uint32_t)((wm * 32 + (lane & 7) + ((lane >> 3) & 1) * 8) * K2_AS
                    + (lane >> 4) * 8)) * 2u;
    const uint32_t bLane =
        ((uint32_t)((wn * 32 + (lane & 7) + ((lane >> 4) & 1) * 8) * K2_AS
                    + ((lane >> 3) & 1) * 8)) * 2u;

#pragma unroll
    for (int j = 0; j < 7; j++) {
        int idx = tid + j * 512;
        int row = idx / 28, c = idx % 28;
        cp16(&sB[row * K2_AS + c * 8], g_wup + (size_t)(n0 + row) * RDIM + c * 8);
    }
    CP_COMMIT();
    CP_WAIT0();
    __syncthreads();

#define K2_LOAD_A64(buf, t64) do {                                              \
    const int mr0 = (t64) * 64;                                                 \
    _Pragma("unroll")                                                           \
    for (int j = 0; j < 7; j++) {                                               \
        int idx = htid + j * 256;                                               \
        int row_ = idx / 28, c_ = idx % 28;                                     \
        cp16(&sA[(half * 2 + (buf)) * K2_T64 + row_ * K2_AS + c_ * 8],          \
             g_mid + (size_t)(mr0 + row_) * RDIM + c_ * 8);                     \
    } } while (0)

    const int t0 = t_begin + half;
    if (t0 < t_end) {
        K2_LOAD_A64(0, t0);
    }
    CP_COMMIT();
    CP_WAIT0();
    BAR_SYNC(1 + half);

    int buf = 0;
    for (int t = t0; t < t_end; t += 2, buf ^= 1) {
        const uint32_t aCur = aU + (uint32_t)((half * 2 + buf) * K2_T64) * 2u;
        const int m0 = t * 64;

        if (t + 2 < t_end) {
            K2_LOAD_A64(buf ^ 1, t + 2);
        }
        CP_COMMIT();

        float acc[2][4][4];
#pragma unroll
        for (int a = 0; a < 2; a++)
#pragma unroll
            for (int b = 0; b < 4; b++)
#pragma unroll
                for (int c = 0; c < 4; c++) acc[a][b][c] = 0.f;

#pragma unroll
        for (int ks = 0; ks < 14; ks++) {
            const uint32_t kOff = (uint32_t)ks * 32u;
            uint32_t a0[4], a1[4], bf[2][4];
            ldsm_x4(a0, aCur + aLane + kOff);
            ldsm_x4(a1, aCur + aLane + (uint32_t)(16 * K2_AS * 2) + kOff);
            ldsm_x4(bf[0], bU + bLane + kOff);
            ldsm_x4(bf[1], bU + bLane + (uint32_t)(16 * K2_AS * 2) + kOff);
            mma_bf16(acc[0][0], a0, bf[0][0], bf[0][1]);
            mma_bf16(acc[0][1], a0, bf[0][2], bf[0][3]);
            mma_bf16(acc[0][2], a0, bf[1][0], bf[1][1]);
            mma_bf16(acc[0][3], a0, bf[1][2], bf[1][3]);
            mma_bf16(acc[1][0], a1, bf[0][0], bf[0][1]);
            mma_bf16(acc[1][1], a1, bf[0][2], bf[0][3]);
            mma_bf16(acc[1][2], a1, bf[1][0], bf[1][1]);
            mma_bf16(acc[1][3], a1, bf[1][2], bf[1][3]);
        }

#pragma unroll
        for (int mt = 0; mt < 2; mt++) {
            const int r0 = m0 + wm * 32 + mt * 16 + gid;
#pragma unroll
            for (int nt = 0; nt < 4; nt++) {
                const int c = n0 + wn * 32 + nt * 8 + tig * 2;
                const size_t i0 = (size_t)r0 * HIDDEN + c;
                const size_t i1 = i0 + (size_t)8 * HIDDEN;
                float2 xv0 = *(const float2*)(x + i0);
                float2 xv1 = *(const float2*)(x + i1);
                float2 o0, o1;
                o0.x = xv0.x + alpha * acc[mt][nt][0];
                o0.y = xv0.y + alpha * acc[mt][nt][1];
                o1.x = xv1.x + alpha * acc[mt][nt][2];
                o1.y = xv1.y + alpha * acc[mt][nt][3];
                *(float2*)(out + i0) = o0;
                *(float2*)(out + i1) = o1;
            }
        }

        if (t + 2 < t_end) {
            CP_WAIT0();
            BAR_SYNC(1 + half);
        }
    }
#undef K2_LOAD_A64
}

// ---------------- launch ----------------
extern "C" void kernel_launch(void* const* d_in, const int* in_sizes, int n_in,
                              void* d_out, int out_size) {
    const float* x     = (const float*)d_in[0];
    const float* gamma = (const float*)d_in[1];
    const float* beta  = (const float*)d_in[2];
    const float* wd    = (const float*)d_in[3];
    const float* wu    = (const float*)d_in[4];
    const float* alpha = (const float*)d_in[5];
    const int tokens = in_sizes[0] / HIDDEN;   // 16384

    prep_all<<<RDIM + 32, 256>>>(wd, gamma, beta, wu);

    const int smem1 = (2 * K1_A64 + 2 * K1_B224) * (int)sizeof(__nv_bfloat16); // 82944
    cudaFuncSetAttribute(kernel_ln_down, cudaFuncAttributeMaxDynamicSharedMemorySize, smem1);
    kernel_ln_down<<<tokens / 64, 256, smem1>>>(x);

    const int smem2 = (128 * K2_AS + 4 * K2_T64) * (int)sizeof(__nv_bfloat16); // 178176
    cudaFuncSetAttribute(kernel_up_res, cudaFuncAttributeMaxDynamicSharedMemorySize, smem2);
    dim3 g2(K2_SPLIT, HIDDEN / 128);
    kernel_up_res<<<g2, 512, smem2>>>(x, alpha, (float*)d_out, tokens / 64);
}

// round 14
// speedup vs baseline: 1.0568x; 1.0568x over previous
#include <cuda_runtime.h>
#include <cuda_bf16.h>
#include <cstdint>

#define HIDDEN 3584
#define RDIM   224
#define MAX_TOKENS 16384

// ---------------- scratch ----------------
__device__ __nv_bfloat16 g_wdp[RDIM * HIDDEN];     // gamma * w_down  [224][3584]
__device__ __nv_bfloat16 g_wup[HIDDEN * RDIM];     // w_up            [3584][224]
__device__ float         g_c1[RDIM];
__device__ float         g_c2[RDIM];
__device__ __nv_bfloat16 g_mid[(size_t)MAX_TOKENS * RDIM];

// ---------------- helpers ----------------
__device__ __forceinline__ uint32_t smem_u32(const void* p) {
    uint32_t a;
    asm("{ .reg .u64 t; cvta.to.shared.u64 t, %1; cvt.u32.u64 %0, t; }" : "=r"(a) : "l"(p));
    return a;
}

__device__ __forceinline__ void mma_bf16(float c[4], const uint32_t* a,
                                         uint32_t b0, uint32_t b1) {
    asm volatile(
        "mma.sync.aligned.m16n8k16.row.col.f32.bf16.bf16.f32 "
        "{%0,%1,%2,%3}, {%4,%5,%6,%7}, {%8,%9}, {%0,%1,%2,%3};\n"
        : "+f"(c[0]), "+f"(c[1]), "+f"(c[2]), "+f"(c[3])
        : "r"(a[0]), "r"(a[1]), "r"(a[2]), "r"(a[3]), "r"(b0), "r"(b1));
}

__device__ __forceinline__ void ldsm_x4(uint32_t* r, uint32_t addr) {
    asm volatile("ldmatrix.sync.aligned.m8n8.x4.shared.b16 {%0,%1,%2,%3}, [%4];"
                 : "=r"(r[0]), "=r"(r[1]), "=r"(r[2]), "=r"(r[3]) : "r"(addr));
}
__device__ __forceinline__ void ldsm_x2(uint32_t* r, uint32_t addr) {
    asm volatile("ldmatrix.sync.aligned.m8n8.x2.shared.b16 {%0,%1}, [%2];"
                 : "=r"(r[0]), "=r"(r[1]) : "r"(addr));
}

__device__ __forceinline__ float gelu_exact(float y) {
    return 0.5f * y * (1.0f + erff(y * 0.70710678118654752f));
}

__device__ __forceinline__ void cp16(void* dst_smem, const void* src_gmem) {
    uint32_t d = (uint32_t)__cvta_generic_to_shared(dst_smem);
    asm volatile("cp.async.cg.shared.global [%0], [%1], 16;\n" :: "r"(d), "l"(src_gmem));
}
#define CP_COMMIT() asm volatile("cp.async.commit_group;\n" ::: "memory")
#define CP_WAIT0()  asm volatile("cp.async.wait_group 0;\n" ::: "memory")
#define BAR_SYNC256(id) asm volatile("bar.sync %0, 256;" :: "r"(id) : "memory")
#define BAR_SYNC128(id) asm volatile("bar.sync %0, 128;" :: "r"(id) : "memory")

// ---------------- merged prep kernel (vectorized) ----------------
__global__ void prep_all(const float* __restrict__ wd, const float* __restrict__ gamma,
                         const float* __restrict__ beta, const float* __restrict__ wu) {
    const int b = blockIdx.x, tid = threadIdx.x;
    if (b < RDIM) {
        const float4* row = (const float4*)(wd + (size_t)b * HIDDEN);
        const float4* g4  = (const float4*)gamma;
        const float4* b4  = (const float4*)beta;
        float c1 = 0.f, c2 = 0.f;
        for (int i = tid; i < HIDDEN / 4; i += 256) {
            float4 w = row[i], g = g4[i], be = b4[i];
            float p0 = g.x * w.x, p1 = g.y * w.y, p2 = g.z * w.z, p3 = g.w * w.w;
            c1 += p0 + p1 + p2 + p3;
            c2 += be.x * w.x + be.y * w.y + be.z * w.z + be.w * w.w;
            __nv_bfloat162 h0 = __floats2bfloat162_rn(p0, p1);
            __nv_bfloat162 h1 = __floats2bfloat162_rn(p2, p3);
            uint2 pk = make_uint2(*(uint32_t*)&h0, *(uint32_t*)&h1);
            *(uint2*)&g_wdp[(size_t)b * HIDDEN + i * 4] = pk;
        }
        __shared__ float s1[256], s2[256];
        s1[tid] = c1; s2[tid] = c2;
        __syncthreads();
        for (int o = 128; o > 0; o >>= 1) {
            if (tid < o) { s1[tid] += s1[tid + o]; s2[tid] += s2[tid + o]; }
            __syncthreads();
        }
        if (tid == 0) { g_c1[b] = s1[0]; g_c2[b] = s2[0]; }
    } else {
        const int blk = b - RDIM;                       // 0..31
        const int n4 = (HIDDEN * RDIM) / 4 / 32;
        const float4* src = (const float4*)wu + (size_t)blk * n4;
        for (int i = tid; i < n4; i += 256) {
            float4 v = src[i];
            __nv_bfloat162 h0 = __floats2bfloat162_rn(v.x, v.y);
            __nv_bfloat162 h1 = __floats2bfloat162_rn(v.z, v.w);
            uint2 pk = make_uint2(*(uint32_t*)&h0, *(uint32_t*)&h1);
            *(uint2*)&g_wup[((size_t)blk * n4 + i) * 4] = pk;
        }
    }
}

// ---------------- kernel 1: fused LN + down-proj + GELU, split-half ---------
// (round-12 winner, unchanged) 128 CTAs, 512 threads, two independent 8-warp
// halves each owning 64 tokens; per-half warp grid 2m x 4n, tile 32x56.
#define K1_AS 72
#define K1_A64 (64 * K1_AS)
#define K1_B224 (RDIM * K1_AS)
#define K1_NCH  (HIDDEN / 64)        // 56

__global__ __launch_bounds__(512, 1)
void kernel_ln_down(const float* __restrict__ x) {
    extern __shared__ __nv_bfloat16 dsm[];
    __nv_bfloat16* sA = dsm;                     // [2 half][2 buf][64][K1_AS]
    __nv_bfloat16* sB = dsm + 4 * K1_A64;        // [2 half][2 buf][224][K1_AS]

    __shared__ float sS1[2][64][4];
    __shared__ float sS2[2][64][4];
    __shared__ float sMu[128], sRstd[128];
    __shared__ float sC1[RDIM], sC2[RDIM];

    const int tid  = threadIdx.x;
    const int warp = tid >> 5, lane = tid & 31;
    const int gid  = lane >> 2, tig = lane & 3;
    const int half = warp >> 3;                  // 0 or 1
    const int w8   = warp & 7;
    const int wm   = w8 >> 2, wn = w8 & 3;       // 2(m) x 4(n); warp tile 32x56
    const int htid = tid & 255;
    const int m0   = blockIdx.x * 128 + half * 64;

    for (int i = tid; i < RDIM; i += 512) { sC1[i] = g_c1[i]; sC2[i] = g_c2[i]; }
    __syncthreads();

    const uint32_t aU = smem_u32(sA), bU = smem_u32(sB);
    const uint32_t aLane =
        ((uint32_t)((wm * 32 + (lane & 7) + ((lane >> 3) & 1) * 8) * K1_AS
                    + (lane >> 4) * 8)) * 2u;
    uint32_t bPair[4];
    {
        const int kc = ((lane >> 3) & 1) * 8;
#pragma unroll
        for (int p = 0; p < 3; p++) {
            int nr = wn * 56 + p * 16 + (lane & 7) + ((lane >> 4) & 1) * 8;
            bPair[p] = (uint32_t)(nr * K1_AS + kc) * 2u;
        }
        int nr3 = wn * 56 + 48 + (lane & 7);
        bPair[3] = (uint32_t)(nr3 * K1_AS + kc) * 2u;
    }

    float acc[2][7][4];
#pragma unroll
    for (int a = 0; a < 2; a++)
#pragma unroll
        for (int b = 0; b < 7; b++)
#pragma unroll
            for (int c = 0; c < 4; c++) acc[a][b][c] = 0.f;

    const int rowx = htid >> 2, lq = htid & 3;
    const float* xr = x + (size_t)(m0 + rowx) * HIDDEN + lq * 16;
    const int brow = htid >> 3, bc8 = htid & 7;
    float s1 = 0.f, s2 = 0.f;

#define K1_FILL_B(buf, ko) do {                                                 \
    __nv_bfloat16* dst_ = sB + (half * 2 + (buf)) * K1_B224;                    \
    _Pragma("unroll")                                                           \
    for (int j = 0; j < 7; j++) {                                               \
        int row_ = brow + j * 32;                                               \
        cp16(&dst_[row_ * K1_AS + bc8 * 8],                                     \
             g_wdp + (size_t)row_ * HIDDEN + (ko) + bc8 * 8);                   \
    } } while (0)

#define K1_LOAD_X(ko, v) do {                                                   \
    _Pragma("unroll")                                                           \
    for (int i = 0; i < 4; i++) (v)[i] = *(const float4*)(xr + (ko) + i * 4);   \
    } while (0)

#define K1_STORE_A(buf, v) do {                                                 \
    _Pragma("unroll")                                                           \
    for (int i = 0; i < 4; i++) {                                               \
        s1 += (v)[i].x + (v)[i].y + (v)[i].z + (v)[i].w;                        \
        s2 += (v)[i].x*(v)[i].x + (v)[i].y*(v)[i].y                             \
            + (v)[i].z*(v)[i].z + (v)[i].w*(v)[i].w;                            \
    }                                                                           \
    {                                                                           \
        __nv_bfloat16* ab_ = sA + (half * 2 + (buf)) * K1_A64;                  \
        uint4 pk;                                                               \
        __nv_bfloat162 t0 = __floats2bfloat162_rn((v)[0].x, (v)[0].y);          \
        __nv_bfloat162 t1 = __floats2bfloat162_rn((v)[0].z, (v)[0].w);          \
        __nv_bfloat162 t2 = __floats2bfloat162_rn((v)[1].x, (v)[1].y);          \
        __nv_bfloat162 t3 = __floats2bfloat162_rn((v)[1].z, (v)[1].w);          \
        pk.x = *(uint32_t*)&t0; pk.y = *(uint32_t*)&t1;                         \
        pk.z = *(uint32_t*)&t2; pk.w = *(uint32_t*)&t3;                         \
        *(uint4*)&ab_[rowx * K1_AS + lq * 16] = pk;                             \
        __nv_bfloat162 u0 = __floats2bfloat162_rn((v)[2].x, (v)[2].y);          \
        __nv_bfloat162 u1 = __floats2bfloat162_rn((v)[2].z, (v)[2].w);          \
        __nv_bfloat162 u2 = __floats2bfloat162_rn((v)[3].x, (v)[3].y);          \
        __nv_bfloat162 u3 = __floats2bfloat162_rn((v)[3].z, (v)[3].w);          \
        pk.x = *(uint32_t*)&u0; pk.y = *(uint32_t*)&u1;                         \
        pk.z = *(uint32_t*)&u2; pk.w = *(uint32_t*)&u3;                         \
        *(uint4*)&ab_[rowx * K1_AS + lq * 16 + 8] = pk;                         \
    } } while (0)

    // ---- per-half prologue ----
    K1_FILL_B(0, 0);
    CP_COMMIT();
    {
        float4 v[4];
        K1_LOAD_X(0, v);
        K1_STORE_A(0, v);
    }
    CP_WAIT0();
    BAR_SYNC256(1 + half);

    // ---- per-half pipelined main loop ----
    for (int it = 0; it < K1_NCH; it++) {
        const int cur = it & 1, nxt = cur ^ 1;
        const uint32_t aCur = aU + (uint32_t)((half * 2 + cur) * K1_A64) * 2u;
        const uint32_t bCur = bU + (uint32_t)((half * 2 + cur) * K1_B224) * 2u;

        float4 v[4];
        if (it < K1_NCH - 1) {
            const int ko = (it + 1) * 64;
            K1_FILL_B(nxt, ko);
            CP_COMMIT();
            K1_LOAD_X(ko, v);
        }

#pragma unroll
        for (int ks = 0; ks < 4; ks++) {
            const uint32_t kOff = (uint32_t)ks * 32u;
            uint32_t a0[4], a1[4];
            ldsm_x4(a0, aCur + aLane + kOff);
            ldsm_x4(a1, aCur + aLane + (uint32_t)(16 * K1_AS * 2) + kOff);
            uint32_t bf[14];
            ldsm_x4(&bf[0],  bCur + bPair[0] + kOff);
            ldsm_x4(&bf[4],  bCur + bPair[1] + kOff);
            ldsm_x4(&bf[8],  bCur + bPair[2] + kOff);
            ldsm_x2(&bf[12], bCur + bPair[3] + kOff);
#pragma unroll
            for (int nt = 0; nt < 7; nt++) {
                mma_bf16(acc[0][nt], a0, bf[2 * nt], bf[2 * nt + 1]);
                mma_bf16(acc[1][nt], a1, bf[2 * nt], bf[2 * nt + 1]);
            }
        }

        if (it < K1_NCH - 1) {
            K1_STORE_A(nxt, v);
            CP_WAIT0();
            BAR_SYNC256(1 + half);
        }
    }

    // ---- per-half row stats ----
    sS1[half][rowx][lq] = s1; sS2[half][rowx][lq] = s2;
    BAR_SYNC256(1 + half);
    if (htid < 64) {
        float t1 = sS1[half][htid][0] + sS1[half][htid][1]
                 + sS1[half][htid][2] + sS1[half][htid][3];
        float t2 = sS2[half][htid][0] + sS2[half][htid][1]
                 + sS2[half][htid][2] + sS2[half][htid][3];
        float mu = t1 * (1.0f / HIDDEN);
        float var = t2 * (1.0f / HIDDEN) - mu * mu;
        sMu[half * 64 + htid] = mu;
        sRstd[half * 64 + htid] = rsqrtf(var + 1e-5f);
    }
    BAR_SYNC256(1 + half);

    // ---- per-half epilogue: LN correction + GELU -> g_mid ----
#pragma unroll
    for (int mt = 0; mt < 2; mt++) {
        const int r0 = wm * 32 + mt * 16 + gid;
        const float mu0 = sMu[half * 64 + r0],     rs0 = sRstd[half * 64 + r0];
        const float mu1 = sMu[half * 64 + r0 + 8], rs1 = sRstd[half * 64 + r0 + 8];
#pragma unroll
        for (int nt = 0; nt < 7; nt++) {
            const int c = wn * 56 + nt * 8 + tig * 2;
            const float c1a = sC1[c], c1b = sC1[c + 1];
            const float c2a = sC2[c], c2b = sC2[c + 1];
            float y00 = rs0 * (acc[mt][nt][0] - mu0 * c1a) + c2a;
            float y01 = rs0 * (acc[mt][nt][1] - mu0 * c1b) + c2b;
            float y10 = rs1 * (acc[mt][nt][2] - mu1 * c1a) + c2a;
            float y11 = rs1 * (acc[mt][nt][3] - mu1 * c1b) + c2b;
            *(__nv_bfloat162*)&g_mid[(size_t)(m0 + r0) * RDIM + c] =
                __floats2bfloat162_rn(gelu_exact(y00), gelu_exact(y01));
            *(__nv_bfloat162*)&g_mid[(size_t)(m0 + r0 + 8) * RDIM + c] =
                __floats2bfloat162_rn(gelu_exact(y10), gelu_exact(y11));
        }
    }
#undef K1_FILL_B
#undef K1_LOAD_X
#undef K1_STORE_A
}

// ---------------- kernel 2: persistent up-proj + residual, split-QUARTER ----
// 140 CTAs (5 m-splits x 28 n-slices), 512 threads. FOUR independent 4-warp
// groups, each owning 32-token tiles with its own A double-buffer and named
// barrier. Per-group warp grid 1m x 4n; warp tile 32x32 (same inner loop as
// the proven round-12 half, just quartered granularity for deeper de-phasing).
#define K2_AS 232
#define K2_SPLIT 5
#define K2_T32 (32 * K2_AS)

__global__ __launch_bounds__(512, 1)
void kernel_up_res(const float* __restrict__ x, const float* __restrict__ alpha_p,
                   float* __restrict__ out, int m_tiles32) {
    extern __shared__ __nv_bfloat16 smem[];
    __nv_bfloat16* sB = smem;                    // [128][K2_AS] resident w_up slice
    __nv_bfloat16* sA = smem + 128 * K2_AS;      // [4 grp][2 buf][32][K2_AS]

    const int tid  = threadIdx.x;
    const int warp = tid >> 5, lane = tid & 31;
    const int gid  = lane >> 2, tig = lane & 3;
    const int qid  = warp >> 2;                  // group 0..3
    const int wn   = warp & 3;                   // 4 n-warps per group
    const int gtid = tid & 127;
    const int n0   = blockIdx.y * 128;
    const int t_begin = (blockIdx.x * m_tiles32) / K2_SPLIT;
    const int t_end   = ((blockIdx.x + 1) * m_tiles32) / K2_SPLIT;

    const float alpha = __ldg(alpha_p);
    const uint32_t bU = smem_u32(sB), aU = smem_u32(sA);
    const uint32_t aLane =
        ((uint32_t)(((lane & 7) + ((lane >> 3) & 1) * 8) * K2_AS
                    + (lane >> 4) * 8)) * 2u;
    const uint32_t bLane =
        ((uint32_t)((wn * 32 + (lane & 7) + ((lane >> 4) & 1) * 8) * K2_AS
                    + ((lane >> 3) & 1) * 8)) * 2u;

    // ---- load resident B slice (all 512 threads), one full sync ----
#pragma unroll
    for (int j = 0; j < 7; j++) {
        int idx = tid + j * 512;                 // 0..3583 = 128 rows x 28
        int row = idx / 28, c = idx % 28;
        cp16(&sB[row * K2_AS + c * 8], g_wup + (size_t)(n0 + row) * RDIM + c * 8);
    }
    CP_COMMIT();
    CP_WAIT0();
    __syncthreads();                             // sB read-only from here on

#define K2_LOAD_A32(buf, t32) do {                                              \
    const int mr0 = (t32) * 32;                                                 \
    _Pragma("unroll")                                                           \
    for (int j = 0; j < 7; j++) {                                               \
        int idx = gtid + j * 128;                /* 32 rows x 28 chunks */      \
        int row_ = idx / 28, c_ = idx % 28;                                     \
        cp16(&sA[(qid * 2 + (buf)) * K2_T32 + row_ * K2_AS + c_ * 8],           \
             g_mid + (size_t)(mr0 + row_) * RDIM + c_ * 8);                     \
    } } while (0)

    // ---- per-group pipeline over tiles t_begin+qid, step 4 ----
    const int t0 = t_begin + qid;
    if (t0 < t_end) {
        K2_LOAD_A32(0, t0);
    }
    CP_COMMIT();
    CP_WAIT0();
    BAR_SYNC128(1 + qid);

    int buf = 0;
    for (int t = t0; t < t_end; t += 4, buf ^= 1) {
        const uint32_t aCur = aU + (uint32_t)((qid * 2 + buf) * K2_T32) * 2u;
        const int m0 = t * 32;

        if (t + 4 < t_end) {
            K2_LOAD_A32(buf ^ 1, t + 4);
        }
        CP_COMMIT();

        float acc[2][4][4];
#pragma unroll
        for (int a = 0; a < 2; a++)
#pragma unroll
            for (int b = 0; b < 4; b++)
#pragma unroll
                for (int c = 0; c < 4; c++) acc[a][b][c] = 0.f;

#pragma unroll
        for (int ks = 0; ks < 14; ks++) {
            const uint32_t kOff = (uint32_t)ks * 32u;
            uint32_t a0[4], a1[4], bf[2][4];
            ldsm_x4(a0, aCur + aLane + kOff);
            ldsm_x4(a1, aCur + aLane + (uint32_t)(16 * K2_AS * 2) + kOff);
            ldsm_x4(bf[0], bU + bLane + kOff);
            ldsm_x4(bf[1], bU + bLane + (uint32_t)(16 * K2_AS * 2) + kOff);
            mma_bf16(acc[0][0], a0, bf[0][0], bf[0][1]);
            mma_bf16(acc[0][1], a0, bf[0][2], bf[0][3]);
            mma_bf16(acc[0][2], a0, bf[1][0], bf[1][1]);
            mma_bf16(acc[0][3], a0, bf[1][2], bf[1][3]);
            mma_bf16(acc[1][0], a1, bf[0][0], bf[0][1]);
            mma_bf16(acc[1][1], a1, bf[0][2], bf[0][3]);
            mma_bf16(acc[1][2], a1, bf[1][0], bf[1][1]);
            mma_bf16(acc[1][3], a1, bf[1][2], bf[1][3]);
        }

        // ---- epilogue: residual add + store ----
#pragma unroll
        for (int mt = 0; mt < 2; mt++) {
            const int r0 = m0 + mt * 16 + gid;
#pragma unroll
            for (int nt = 0; nt < 4; nt++) {
                const int c = n0 + wn * 32 + nt * 8 + tig * 2;
                const size_t i0 = (size_t)r0 * HIDDEN + c;
                const size_t i1 = i0 + (size_t)8 * HIDDEN;
                float2 xv0 = *(const float2*)(x + i0);
                float2 xv1 = *(const float2*)(x + i1);
                float2 o0, o1;
                o0.x = xv0.x + alpha * acc[mt][nt][0];
                o0.y = xv0.y + alpha * acc[mt][nt][1];
                o1.x = xv1.x + alpha * acc[mt][nt][2];
                o1.y = xv1.y + alpha * acc[mt][nt][3];
                *(float2*)(out + i0) = o0;
                *(float2*)(out + i1) = o1;
            }
        }

        if (t + 4 < t_end) {
            CP_WAIT0();
            BAR_SYNC128(1 + qid);
        }
    }
#undef K2_LOAD_A32
}

// ---------------- launch ----------------
extern "C" void kernel_launch(void* const* d_in, const int* in_sizes, int n_in,
                              void* d_out, int out_size) {
    const float* x     = (const float*)d_in[0];
    const float* gamma = (const float*)d_in[1];
    const float* beta  = (const float*)d_in[2];
    const float* wd    = (const float*)d_in[3];
    const float* wu    = (const float*)d_in[4];
    const float* alpha = (const float*)d_in[5];
    const int tokens = in_sizes[0] / HIDDEN;   // 16384

    prep_all<<<RDIM + 32, 256>>>(wd, gamma, beta, wu);

    const int smem1 = (4 * K1_A64 + 4 * K1_B224) * (int)sizeof(__nv_bfloat16); // 165888
    cudaFuncSetAttribute(kernel_ln_down, cudaFuncAttributeMaxDynamicSharedMemorySize, smem1);
    kernel_ln_down<<<tokens / 128, 512, smem1>>>(x);

    const int smem2 = (128 * K2_AS + 8 * K2_T32) * (int)sizeof(__nv_bfloat16); // 178176
    cudaFuncSetAttribute(kernel_up_res, cudaFuncAttributeMaxDynamicSharedMemorySize, smem2);
    dim3 g2(K2_SPLIT, HIDDEN / 128);
    kernel_up_res<<<g2, 512, smem2>>>(x, alpha, (float*)d_out, tokens / 32);
}

// round 15
// speedup vs baseline: 1.0675x; 1.0101x over previous
#include <cuda_runtime.h>
#include <cuda_bf16.h>
#include <cstdint>

#define HIDDEN 3584
#define RDIM   224
#define MAX_TOKENS 16384

// ---------------- scratch ----------------
__device__ __nv_bfloat16 g_wdp[RDIM * HIDDEN];     // gamma * w_down  [224][3584]
__device__ __nv_bfloat16 g_wup[HIDDEN * RDIM];     // w_up            [3584][224]
__device__ float         g_c1[RDIM];
__device__ float         g_c2[RDIM];
__device__ __nv_bfloat16 g_mid[(size_t)MAX_TOKENS * RDIM];

// ---------------- helpers ----------------
__device__ __forceinline__ uint32_t smem_u32(const void* p) {
    uint32_t a;
    asm("{ .reg .u64 t; cvta.to.shared.u64 t, %1; cvt.u32.u64 %0, t; }" : "=r"(a) : "l"(p));
    return a;
}

__device__ __forceinline__ void mma_bf16(float c[4], const uint32_t* a,
                                         uint32_t b0, uint32_t b1) {
    asm volatile(
        "mma.sync.aligned.m16n8k16.row.col.f32.bf16.bf16.f32 "
        "{%0,%1,%2,%3}, {%4,%5,%6,%7}, {%8,%9}, {%0,%1,%2,%3};\n"
        : "+f"(c[0]), "+f"(c[1]), "+f"(c[2]), "+f"(c[3])
        : "r"(a[0]), "r"(a[1]), "r"(a[2]), "r"(a[3]), "r"(b0), "r"(b1));
}

__device__ __forceinline__ void ldsm_x4(uint32_t* r, uint32_t addr) {
    asm volatile("ldmatrix.sync.aligned.m8n8.x4.shared.b16 {%0,%1,%2,%3}, [%4];"
                 : "=r"(r[0]), "=r"(r[1]), "=r"(r[2]), "=r"(r[3]) : "r"(addr));
}
__device__ __forceinline__ void ldsm_x2(uint32_t* r, uint32_t addr) {
    asm volatile("ldmatrix.sync.aligned.m8n8.x2.shared.b16 {%0,%1}, [%2];"
                 : "=r"(r[0]), "=r"(r[1]) : "r"(addr));
}

__device__ __forceinline__ float gelu_exact(float y) {
    return 0.5f * y * (1.0f + erff(y * 0.70710678118654752f));
}

__device__ __forceinline__ void cp16(void* dst_smem, const void* src_gmem) {
    uint32_t d = (uint32_t)__cvta_generic_to_shared(dst_smem);
    asm volatile("cp.async.cg.shared.global [%0], [%1], 16;\n" :: "r"(d), "l"(src_gmem));
}
#define CP_COMMIT() asm volatile("cp.async.commit_group;\n" ::: "memory")
#define CP_WAIT0()  asm volatile("cp.async.wait_group 0;\n" ::: "memory")
#define BAR_SYNC256(id) asm volatile("bar.sync %0, 256;" :: "r"(id) : "memory")
#define BAR_SYNC128(id) asm volatile("bar.sync %0, 128;" :: "r"(id) : "memory")

// ---------------- merged prep kernel (vectorized) ----------------
__global__ void prep_all(const float* __restrict__ wd, const float* __restrict__ gamma,
                         const float* __restrict__ beta, const float* __restrict__ wu) {
    const int b = blockIdx.x, tid = threadIdx.x;
    if (b < RDIM) {
        const float4* row = (const float4*)(wd + (size_t)b * HIDDEN);
        const float4* g4  = (const float4*)gamma;
        const float4* b4  = (const float4*)beta;
        float c1 = 0.f, c2 = 0.f;
        for (int i = tid; i < HIDDEN / 4; i += 256) {
            float4 w = row[i], g = g4[i], be = b4[i];
            float p0 = g.x * w.x, p1 = g.y * w.y, p2 = g.z * w.z, p3 = g.w * w.w;
            c1 += p0 + p1 + p2 + p3;
            c2 += be.x * w.x + be.y * w.y + be.z * w.z + be.w * w.w;
            __nv_bfloat162 h0 = __floats2bfloat162_rn(p0, p1);
            __nv_bfloat162 h1 = __floats2bfloat162_rn(p2, p3);
            uint2 pk = make_uint2(*(uint32_t*)&h0, *(uint32_t*)&h1);
            *(uint2*)&g_wdp[(size_t)b * HIDDEN + i * 4] = pk;
        }
        __shared__ float s1[256], s2[256];
        s1[tid] = c1; s2[tid] = c2;
        __syncthreads();
        for (int o = 128; o > 0; o >>= 1) {
            if (tid < o) { s1[tid] += s1[tid + o]; s2[tid] += s2[tid + o]; }
            __syncthreads();
        }
        if (tid == 0) { g_c1[b] = s1[0]; g_c2[b] = s2[0]; }
    } else {
        const int blk = b - RDIM;                       // 0..31
        const int n4 = (HIDDEN * RDIM) / 4 / 32;
        const float4* src = (const float4*)wu + (size_t)blk * n4;
        for (int i = tid; i < n4; i += 256) {
            float4 v = src[i];
            __nv_bfloat162 h0 = __floats2bfloat162_rn(v.x, v.y);
            __nv_bfloat162 h1 = __floats2bfloat162_rn(v.z, v.w);
            uint2 pk = make_uint2(*(uint32_t*)&h0, *(uint32_t*)&h1);
            *(uint2*)&g_wup[((size_t)blk * n4 + i) * 4] = pk;
        }
    }
}

// ---------------- kernel 1: fused LN + down-proj + GELU, split-half + PDL ---
// 128 CTAs, 512 threads, two independent 8-warp halves each owning 64 tokens.
// Chunk-0 x tile loaded BEFORE the grid dependency sync (prep-independent).
#define K1_AS 72
#define K1_A64 (64 * K1_AS)
#define K1_B224 (RDIM * K1_AS)
#define K1_NCH  (HIDDEN / 64)        // 56

__global__ __launch_bounds__(512, 1)
void kernel_ln_down(const float* __restrict__ x) {
    extern __shared__ __nv_bfloat16 dsm[];
    __nv_bfloat16* sA = dsm;                     // [2 half][2 buf][64][K1_AS]
    __nv_bfloat16* sB = dsm + 4 * K1_A64;        // [2 half][2 buf][224][K1_AS]

    __shared__ float sS1[2][64][4];
    __shared__ float sS2[2][64][4];
    __shared__ float sMu[128], sRstd[128];
    __shared__ float sC1[RDIM], sC2[RDIM];

    const int tid  = threadIdx.x;
    const int warp = tid >> 5, lane = tid & 31;
    const int gid  = lane >> 2, tig = lane & 3;
    const int half = warp >> 3;                  // 0 or 1
    const int w8   = warp & 7;
    const int wm   = w8 >> 2, wn = w8 & 3;       // 2(m) x 4(n); warp tile 32x56
    const int htid = tid & 255;
    const int m0   = blockIdx.x * 128 + half * 64;

    const uint32_t aU = smem_u32(sA), bU = smem_u32(sB);
    const uint32_t aLane =
        ((uint32_t)((wm * 32 + (lane & 7) + ((lane >> 3) & 1) * 8) * K1_AS
                    + (lane >> 4) * 8)) * 2u;
    uint32_t bPair[4];
    {
        const int kc = ((lane >> 3) & 1) * 8;
#pragma unroll
        for (int p = 0; p < 3; p++) {
            int nr = wn * 56 + p * 16 + (lane & 7) + ((lane >> 4) & 1) * 8;
            bPair[p] = (uint32_t)(nr * K1_AS + kc) * 2u;
        }
        int nr3 = wn * 56 + 48 + (lane & 7);
        bPair[3] = (uint32_t)(nr3 * K1_AS + kc) * 2u;
    }

    float acc[2][7][4];
#pragma unroll
    for (int a = 0; a < 2; a++)
#pragma unroll
        for (int b = 0; b < 7; b++)
#pragma unroll
            for (int c = 0; c < 4; c++) acc[a][b][c] = 0.f;

    const int rowx = htid >> 2, lq = htid & 3;
    const float* xr = x + (size_t)(m0 + rowx) * HIDDEN + lq * 16;
    const int brow = htid >> 3, bc8 = htid & 7;
    float s1 = 0.f, s2 = 0.f;

#define K1_FILL_B(buf, ko) do {                                                 \
    __nv_bfloat16* dst_ = sB + (half * 2 + (buf)) * K1_B224;                    \
    _Pragma("unroll")                                                           \
    for (int j = 0; j < 7; j++) {                                               \
        int row_ = brow + j * 32;                                               \
        cp16(&dst_[row_ * K1_AS + bc8 * 8],                                     \
             g_wdp + (size_t)row_ * HIDDEN + (ko) + bc8 * 8);                   \
    } } while (0)

#define K1_LOAD_X(ko, v) do {                                                   \
    _Pragma("unroll")                                                           \
    for (int i = 0; i < 4; i++) (v)[i] = *(const float4*)(xr + (ko) + i * 4);   \
    } while (0)

#define K1_STORE_A(buf, v) do {                                                 \
    _Pragma("unroll")                                                           \
    for (int i = 0; i < 4; i++) {                                               \
        s1 += (v)[i].x + (v)[i].y + (v)[i].z + (v)[i].w;                        \
        s2 += (v)[i].x*(v)[i].x + (v)[i].y*(v)[i].y                             \
            + (v)[i].z*(v)[i].z + (v)[i].w*(v)[i].w;                            \
    }                                                                           \
    {                                                                           \
        __nv_bfloat16* ab_ = sA + (half * 2 + (buf)) * K1_A64;                  \
        uint4 pk;                                                               \
        __nv_bfloat162 t0 = __floats2bfloat162_rn((v)[0].x, (v)[0].y);          \
        __nv_bfloat162 t1 = __floats2bfloat162_rn((v)[0].z, (v)[0].w);          \
        __nv_bfloat162 t2 = __floats2bfloat162_rn((v)[1].x, (v)[1].y);          \
        __nv_bfloat162 t3 = __floats2bfloat162_rn((v)[1].z, (v)[1].w);          \
        pk.x = *(uint32_t*)&t0; pk.y = *(uint32_t*)&t1;                         \
        pk.z = *(uint32_t*)&t2; pk.w = *(uint32_t*)&t3;                         \
        *(uint4*)&ab_[rowx * K1_AS + lq * 16] = pk;                             \
        __nv_bfloat162 u0 = __floats2bfloat162_rn((v)[2].x, (v)[2].y);          \
        __nv_bfloat162 u1 = __floats2bfloat162_rn((v)[2].z, (v)[2].w);          \
        __nv_bfloat162 u2 = __floats2bfloat162_rn((v)[3].x, (v)[3].y);          \
        __nv_bfloat162 u3 = __floats2bfloat162_rn((v)[3].z, (v)[3].w);          \
        pk.x = *(uint32_t*)&u0; pk.y = *(uint32_t*)&u1;                         \
        pk.z = *(uint32_t*)&u2; pk.w = *(uint32_t*)&u3;                         \
        *(uint4*)&ab_[rowx * K1_AS + lq * 16 + 8] = pk;                         \
    } } while (0)

    // ---- PDL: x chunk-0 load is prep-independent; do it before the sync ----
    {
        float4 v[4];
        K1_LOAD_X(0, v);
        K1_STORE_A(0, v);
    }
    cudaGridDependencySynchronize();             // wait for prep_all outputs

    for (int i = tid; i < RDIM; i += 512) { sC1[i] = g_c1[i]; sC2[i] = g_c2[i]; }
    K1_FILL_B(0, 0);
    CP_COMMIT();
    CP_WAIT0();
    BAR_SYNC256(1 + half);

    // ---- per-half pipelined main loop ----
    for (int it = 0; it < K1_NCH; it++) {
        const int cur = it & 1, nxt = cur ^ 1;
        const uint32_t aCur = aU + (uint32_t)((half * 2 + cur) * K1_A64) * 2u;
        const uint32_t bCur = bU + (uint32_t)((half * 2 + cur) * K1_B224) * 2u;

        float4 v[4];
        if (it < K1_NCH - 1) {
            const int ko = (it + 1) * 64;
            K1_FILL_B(nxt, ko);
            CP_COMMIT();
            K1_LOAD_X(ko, v);
        }

#pragma unroll
        for (int ks = 0; ks < 4; ks++) {
            const uint32_t kOff = (uint32_t)ks * 32u;
            uint32_t a0[4], a1[4];
            ldsm_x4(a0, aCur + aLane + kOff);
            ldsm_x4(a1, aCur + aLane + (uint32_t)(16 * K1_AS * 2) + kOff);
            uint32_t bf[14];
            ldsm_x4(&bf[0],  bCur + bPair[0] + kOff);
            ldsm_x4(&bf[4],  bCur + bPair[1] + kOff);
            ldsm_x4(&bf[8],  bCur + bPair[2] + kOff);
            ldsm_x2(&bf[12], bCur + bPair[3] + kOff);
#pragma unroll
            for (int nt = 0; nt < 7; nt++) {
                mma_bf16(acc[0][nt], a0, bf[2 * nt], bf[2 * nt + 1]);
                mma_bf16(acc[1][nt], a1, bf[2 * nt], bf[2 * nt + 1]);
            }
        }

        if (it < K1_NCH - 1) {
            K1_STORE_A(nxt, v);
            CP_WAIT0();
            BAR_SYNC256(1 + half);
        }
    }

    // ---- per-half row stats ----
    sS1[half][rowx][lq] = s1; sS2[half][rowx][lq] = s2;
    BAR_SYNC256(1 + half);
    if (htid < 64) {
        float t1 = sS1[half][htid][0] + sS1[half][htid][1]
                 + sS1[half][htid][2] + sS1[half][htid][3];
        float t2 = sS2[half][htid][0] + sS2[half][htid][1]
                 + sS2[half][htid][2] + sS2[half][htid][3];
        float mu = t1 * (1.0f / HIDDEN);
        float var = t2 * (1.0f / HIDDEN) - mu * mu;
        sMu[half * 64 + htid] = mu;
        sRstd[half * 64 + htid] = rsqrtf(var + 1e-5f);
    }
    BAR_SYNC256(1 + half);

    // ---- per-half epilogue: LN correction + GELU -> g_mid ----
#pragma unroll
    for (int mt = 0; mt < 2; mt++) {
        const int r0 = wm * 32 + mt * 16 + gid;
        const float mu0 = sMu[half * 64 + r0],     rs0 = sRstd[half * 64 + r0];
        const float mu1 = sMu[half * 64 + r0 + 8], rs1 = sRstd[half * 64 + r0 + 8];
#pragma unroll
        for (int nt = 0; nt < 7; nt++) {
            const int c = wn * 56 + nt * 8 + tig * 2;
            const float c1a = sC1[c], c1b = sC1[c + 1];
            const float c2a = sC2[c], c2b = sC2[c + 1];
            float y00 = rs0 * (acc[mt][nt][0] - mu0 * c1a) + c2a;
            float y01 = rs0 * (acc[mt][nt][1] - mu0 * c1b) + c2b;
            float y10 = rs1 * (acc[mt][nt][2] - mu1 * c1a) + c2a;
            float y11 = rs1 * (acc[mt][nt][3] - mu1 * c1b) + c2b;
            *(__nv_bfloat162*)&g_mid[(size_t)(m0 + r0) * RDIM + c] =
                __floats2bfloat162_rn(gelu_exact(y00), gelu_exact(y01));
            *(__nv_bfloat162*)&g_mid[(size_t)(m0 + r0 + 8) * RDIM + c] =
                __floats2bfloat162_rn(gelu_exact(y10), gelu_exact(y11));
        }
    }
#undef K1_FILL_B
#undef K1_LOAD_X
#undef K1_STORE_A
}

// ---------------- kernel 2: persistent up-proj + residual, quarters + PDL ---
// 140 CTAs (5 m-splits x 28 n-slices), 512 threads, four independent 4-warp
// groups on 32-token tiles. w_up slice (k1-independent) staged BEFORE the
// grid dependency sync so its load overlaps k1's tail.
#define K2_AS 232
#define K2_SPLIT 5
#define K2_T32 (32 * K2_AS)

__global__ __launch_bounds__(512, 1)
void kernel_up_res(const float* __restrict__ x, const float* __restrict__ alpha_p,
                   float* __restrict__ out, int m_tiles32) {
    extern __shared__ __nv_bfloat16 smem[];
    __nv_bfloat16* sB = smem;                    // [128][K2_AS] resident w_up slice
    __nv_bfloat16* sA = smem + 128 * K2_AS;      // [4 grp][2 buf][32][K2_AS]

    const int tid  = threadIdx.x;
    const int warp = tid >> 5, lane = tid & 31;
    const int gid  = lane >> 2, tig = lane & 3;
    const int qid  = warp >> 2;                  // group 0..3
    const int wn   = warp & 3;
    const int gtid = tid & 127;
    const int n0   = blockIdx.y * 128;
    const int t_begin = (blockIdx.x * m_tiles32) / K2_SPLIT;
    const int t_end   = ((blockIdx.x + 1) * m_tiles32) / K2_SPLIT;

    const uint32_t bU = smem_u32(sB), aU = smem_u32(sA);
    const uint32_t aLane =
        ((uint32_t)(((lane & 7) + ((lane >> 3) & 1) * 8) * K2_AS
                    + (lane >> 4) * 8)) * 2u;
    const uint32_t bLane =
        ((uint32_t)((wn * 32 + (lane & 7) + ((lane >> 4) & 1) * 8) * K2_AS
                    + ((lane >> 3) & 1) * 8)) * 2u;

    // ---- PDL: stage w_up slice (k1-independent) before the sync ----
#pragma unroll
    for (int j = 0; j < 7; j++) {
        int idx = tid + j * 512;                 // 0..3583 = 128 rows x 28
        int row = idx / 28, c = idx % 28;
        cp16(&sB[row * K2_AS + c * 8], g_wup + (size_t)(n0 + row) * RDIM + c * 8);
    }
    CP_COMMIT();

    cudaGridDependencySynchronize();             // wait for k1's g_mid

    const float alpha = __ldg(alpha_p);
    CP_WAIT0();
    __syncthreads();                             // sB read-only from here on

#define K2_LOAD_A32(buf, t32) do {                                              \
    const int mr0 = (t32) * 32;                                                 \
    _Pragma("unroll")                                                           \
    for (int j = 0; j < 7; j++) {                                               \
        int idx = gtid + j * 128;                /* 32 rows x 28 chunks */      \
        int row_ = idx / 28, c_ = idx % 28;                                     \
        cp16(&sA[(qid * 2 + (buf)) * K2_T32 + row_ * K2_AS + c_ * 8],           \
             g_mid + (size_t)(mr0 + row_) * RDIM + c_ * 8);                     \
    } } while (0)

    const int t0 = t_begin + qid;
    if (t0 < t_end) {
        K2_LOAD_A32(0, t0);
    }
    CP_COMMIT();
    CP_WAIT0();
    BAR_SYNC128(1 + qid);

    int buf = 0;
    for (int t = t0; t < t_end; t += 4, buf ^= 1) {
        const uint32_t aCur = aU + (uint32_t)((qid * 2 + buf) * K2_T32) * 2u;
        const int m0 = t * 32;

        if (t + 4 < t_end) {
            K2_LOAD_A32(buf ^ 1, t + 4);
        }
        CP_COMMIT();

        float acc[2][4][4];
#pragma unroll
        for (int a = 0; a < 2; a++)
#pragma unroll
            for (int b = 0; b < 4; b++)
#pragma unroll
                for (int c = 0; c < 4; c++) acc[a][b][c] = 0.f;

#pragma unroll
        for (int ks = 0; ks < 14; ks++) {
            const uint32_t kOff = (uint32_t)ks * 32u;
            uint32_t a0[4], a1[4], bf[2][4];
            ldsm_x4(a0, aCur + aLane + kOff);
            ldsm_x4(a1, aCur + aLane + (uint32_t)(16 * K2_AS * 2) + kOff);
            ldsm_x4(bf[0], bU + bLane + kOff);
            ldsm_x4(bf[1], bU + bLane + (uint32_t)(16 * K2_AS * 2) + kOff);
            mma_bf16(acc[0][0], a0, bf[0][0], bf[0][1]);
            mma_bf16(acc[0][1], a0, bf[0][2], bf[0][3]);
            mma_bf16(acc[0][2], a0, bf[1][0], bf[1][1]);
            mma_bf16(acc[0][3], a0, bf[1][2], bf[1][3]);
            mma_bf16(acc[1][0], a1, bf[0][0], bf[0][1]);
            mma_bf16(acc[1][1], a1, bf[0][2], bf[0][3]);
            mma_bf16(acc[1][2], a1, bf[1][0], bf[1][1]);
            mma_bf16(acc[1][3], a1, bf[1][2], bf[1][3]);
        }

        // ---- epilogue: residual add + store ----
#pragma unroll
        for (int mt = 0; mt < 2; mt++) {
            const int r0 = m0 + mt * 16 + gid;
#pragma unroll
            for (int nt = 0; nt < 4; nt++) {
                const int c = n0 + wn * 32 + nt * 8 + tig * 2;
                const size_t i0 = (size_t)r0 * HIDDEN + c;
                const size_t i1 = i0 + (size_t)8 * HIDDEN;
                float2 xv0 = *(const float2*)(x + i0);
                float2 xv1 = *(const float2*)(x + i1);
                float2 o0, o1;
                o0.x = xv0.x + alpha * acc[mt][nt][0];
                o0.y = xv0.y + alpha * acc[mt][nt][1];
                o1.x = xv1.x + alpha * acc[mt][nt][2];
                o1.y = xv1.y + alpha * acc[mt][nt][3];
                *(float2*)(out + i0) = o0;
                *(float2*)(out + i1) = o1;
            }
        }

        if (t + 4 < t_end) {
            CP_WAIT0();
            BAR_SYNC128(1 + qid);
        }
    }
#undef K2_LOAD_A32
}

// ---------------- launch ----------------
extern "C" void kernel_launch(void* const* d_in, const int* in_sizes, int n_in,
                              void* d_out, int out_size) {
    const float* x     = (const float*)d_in[0];
    const float* gamma = (const float*)d_in[1];
    const float* beta  = (const float*)d_in[2];
    const float* wd    = (const float*)d_in[3];
    const float* wu    = (const float*)d_in[4];
    const float* alpha = (const float*)d_in[5];
    const int tokens = in_sizes[0] / HIDDEN;   // 16384

    prep_all<<<RDIM + 32, 256>>>(wd, gamma, beta, wu);

    const int smem1 = (4 * K1_A64 + 4 * K1_B224) * (int)sizeof(__nv_bfloat16); // 165888
    cudaFuncSetAttribute(kernel_ln_down, cudaFuncAttributeMaxDynamicSharedMemorySize, smem1);
    {
        cudaLaunchConfig_t cfg = {};
        cfg.gridDim = dim3(tokens / 128, 1, 1);
        cfg.blockDim = dim3(512, 1, 1);
        cfg.dynamicSmemBytes = smem1;
        cudaLaunchAttribute at[1];
        at[0].id = cudaLaunchAttributeProgrammaticStreamSerialization;
        at[0].val.programmaticStreamSerializationAllowed = 1;
        cfg.attrs = at;
        cfg.numAttrs = 1;
        cudaLaunchKernelEx(&cfg, kernel_ln_down, x);
    }

    const int smem2 = (128 * K2_AS + 8 * K2_T32) * (int)sizeof(__nv_bfloat16); // 178176
    cudaFuncSetAttribute(kernel_up_res, cudaFuncAttributeMaxDynamicSharedMemorySize, smem2);
    {
        cudaLaunchConfig_t cfg = {};
        cfg.gridDim = dim3(K2_SPLIT, HIDDEN / 128, 1);
        cfg.blockDim = dim3(512, 1, 1);
        cfg.dynamicSmemBytes = smem2;
        cudaLaunchAttribute at[1];
        at[0].id = cudaLaunchAttributeProgrammaticStreamSerialization;
        at[0].val.programmaticStreamSerializationAllowed = 1;
        cfg.attrs = at;
        cfg.numAttrs = 1;
        cudaLaunchKernelEx(&cfg, kernel_up_res, x, alpha, (float*)d_out, tokens / 32);
    }
}